// round 1
// baseline (speedup 1.0000x reference)
#include <cuda_runtime.h>

#define Bb 32
#define Cc 8
#define Ll 4096
#define Kk 128
#define Ss 64
#define Ww (Ll - Ss + 1)        /* 4033 */
#define WT 128                  /* window tile per CTA */
#define NWT ((Ww + WT - 1) / WT) /* 32 tiles */
#define SH_STRIDE 65            /* padded smem stride for shapelet tile */

__global__ void init_out_kernel(float* out) {
    int i = blockIdx.x * blockDim.x + threadIdx.x;
    if (i < Bb * Kk) out[i] = __int_as_float(0x7f7fffff); /* FLT_MAX */
}

__global__ __launch_bounds__(256, 1)
void shapelet_min_kernel(const float* __restrict__ x,
                         const float* __restrict__ sh,
                         float* __restrict__ out) {
    __shared__ float sh_s[Kk * SH_STRIDE];   /* 33280 B: one channel's shapelets */
    __shared__ float x_s[WT + Ss];           /* 192 floats: x window segment */
    __shared__ float xn_s[WT];               /* sliding ||x||^2 */
    __shared__ float sn_s[Kk];               /* shapelet ||.||^2 */

    const int b   = blockIdx.y;
    const int w0  = blockIdx.x * WT;
    const int tid = threadIdx.x;
    const int tx  = tid & 15;   /* w-dimension of thread grid (16) */
    const int ty  = tid >> 4;   /* k-dimension of thread grid (16) */

    /* acc[i][j]: sum over channels of distances for k = ty*8+i, w = w0 + tx + 16*j */
    float acc[8][8];
    #pragma unroll
    for (int i = 0; i < 8; i++)
        #pragma unroll
        for (int j = 0; j < 8; j++) acc[i][j] = 0.0f;

    for (int c = 0; c < Cc; c++) {
        __syncthreads();  /* protect smem reads from previous channel */

        /* load x segment for this (b,c), zero-padded past L */
        for (int idx = tid; idx < WT + Ss; idx += 256) {
            int g = w0 + idx;
            x_s[idx] = (g < Ll) ? x[(b * Cc + c) * Ll + g] : 0.0f;
        }
        /* load shapelets[c] (128x64) via float4, scatter into padded smem */
        {
            const float4* shc4 = (const float4*)(sh + c * Kk * Ss);
            #pragma unroll
            for (int idx = tid; idx < (Kk * Ss) / 4; idx += 256) {
                float4 v = shc4[idx];
                int e = idx * 4;
                int k = e >> 6;       /* /64 */
                int s = e & 63;
                float* p = &sh_s[k * SH_STRIDE + s];
                p[0] = v.x; p[1] = v.y; p[2] = v.z; p[3] = v.w;
            }
        }
        __syncthreads();

        /* norms: threads 0..127 -> xnorm per window, 128..255 -> snorm per shapelet */
        if (tid < WT) {
            float t = 0.0f;
            #pragma unroll 16
            for (int s = 0; s < Ss; s++) { float v = x_s[tid + s]; t = fmaf(v, v, t); }
            xn_s[tid] = t;
        } else {
            int k = tid - 128;
            float t = 0.0f;
            #pragma unroll 16
            for (int s = 0; s < Ss; s++) { float v = sh_s[k * SH_STRIDE + s]; t = fmaf(v, v, t); }
            sn_s[k] = t;
        }
        __syncthreads();

        /* 128x128x64 register-blocked GEMM: cr[i][j] = <sh[k], x[w..w+S]> */
        float cr[8][8];
        #pragma unroll
        for (int i = 0; i < 8; i++)
            #pragma unroll
            for (int j = 0; j < 8; j++) cr[i][j] = 0.0f;

        #pragma unroll 8
        for (int s = 0; s < Ss; s++) {
            float xv[8], sv[8];
            #pragma unroll
            for (int j = 0; j < 8; j++) xv[j] = x_s[tx + 16 * j + s];
            #pragma unroll
            for (int i = 0; i < 8; i++) sv[i] = sh_s[(ty * 8 + i) * SH_STRIDE + s];
            #pragma unroll
            for (int i = 0; i < 8; i++)
                #pragma unroll
                for (int j = 0; j < 8; j++)
                    cr[i][j] = fmaf(sv[i], xv[j], cr[i][j]);
        }

        /* epilogue: d = sqrt(max(xn + sn - 2*cross, eps)), accumulate over channels */
        #pragma unroll
        for (int i = 0; i < 8; i++) {
            float sn = sn_s[ty * 8 + i];
            #pragma unroll
            for (int j = 0; j < 8; j++) {
                float d2 = fmaf(-2.0f, cr[i][j], xn_s[tx + 16 * j] + sn);
                d2 = fmaxf(d2, 1e-12f);
                acc[i][j] += d2 * rsqrtf(d2);   /* sqrt via single MUFU.RSQ + FMUL */
            }
        }
    }

    /* min over w within tile, then global atomic min (positive floats == int order) */
    __syncthreads();
    float* red = sh_s;  /* reuse: 128 x 16 floats */
    #pragma unroll
    for (int i = 0; i < 8; i++) {
        float m = 3.4e38f;
        #pragma unroll
        for (int j = 0; j < 8; j++) {
            int w = w0 + tx + 16 * j;
            if (w < Ww) m = fminf(m, acc[i][j]);
        }
        red[(ty * 8 + i) * 16 + tx] = m;
    }
    __syncthreads();
    if (tid < Kk) {
        float m = 3.4e38f;
        #pragma unroll
        for (int t = 0; t < 16; t++) m = fminf(m, red[tid * 16 + t]);
        atomicMin((int*)&out[b * Kk + tid], __float_as_int(m));
    }
}

extern "C" void kernel_launch(void* const* d_in, const int* in_sizes, int n_in,
                              void* d_out, int out_size) {
    const float* x  = (const float*)d_in[0];   /* (32, 8, 4096) */
    const float* sh = (const float*)d_in[1];   /* (8, 128, 64)  */
    float* out = (float*)d_out;                /* (32, 1, 128)  */

    init_out_kernel<<<(Bb * Kk + 255) / 256, 256>>>(out);
    dim3 grid(NWT, Bb);
    shapelet_min_kernel<<<grid, 256>>>(x, sh, out);
}

// round 4
// speedup vs baseline: 1.3874x; 1.3874x over previous
#include <cuda_runtime.h>
#include <cuda_bf16.h>
#include <cstdint>

#define Bb 32
#define Cc 8
#define Ll 4096
#define Kk 128
#define Ss 64
#define Ww (Ll - Ss + 1)          /* 4033 */
#define WT 64                     /* windows per CTA */
#define NWT ((Ww + WT - 1) / WT)  /* 64 */
#define APITCH 72                 /* padded row pitch in bf16 elems (144 B) */
#define RPB (APITCH * 2)          /* row pitch bytes */

/* ---- scratch (device globals; no allocation allowed) ---- */
__device__ __nv_bfloat16 g_x_hi[Bb * Cc * Ll];
__device__ __nv_bfloat16 g_x_lo[Bb * Cc * Ll];
__device__ __nv_bfloat16 g_sh_hi[Cc * Kk * Ss];
__device__ __nv_bfloat16 g_sh_lo[Cc * Kk * Ss];
__device__ float         g_sn[Cc * Kk];

/* ---- smem layout (bytes) ---- */
#define SM_AH   0
#define SM_AL   (SM_AH + Kk * RPB)        /* 18432 */
#define SM_BH   (SM_AL + Kk * RPB)        /* 36864 */
#define SM_BL   (SM_BH + WT * RPB)        /* 46080 */
#define SM_XSEG (SM_BL + WT * RPB)        /* 55296: 4 arrays x 160 bf16 */
#define SM_XN   (SM_XSEG + 4 * 160 * 2)   /* 56576: 64 f32 */
#define SM_SN   (SM_XN + WT * 4)          /* 56832: 1024 f32 */
#define SM_TOTAL (SM_SN + Cc * Kk * 4)    /* 60928 */

__device__ __forceinline__ uint32_t smem_u32(const void* p) {
    uint32_t a;
    asm("{ .reg .u64 t; cvta.to.shared.u64 t, %1; cvt.u32.u64 %0, t; }" : "=r"(a) : "l"(p));
    return a;
}
__device__ __forceinline__ void ldsm_x4(uint32_t* r, uint32_t addr) {
    asm volatile("ldmatrix.sync.aligned.m8n8.x4.shared.b16 {%0,%1,%2,%3}, [%4];"
                 : "=r"(r[0]), "=r"(r[1]), "=r"(r[2]), "=r"(r[3]) : "r"(addr));
}
__device__ __forceinline__ void ldsm_x2(uint32_t* r, uint32_t addr) {
    asm volatile("ldmatrix.sync.aligned.m8n8.x2.shared.b16 {%0,%1}, [%2];"
                 : "=r"(r[0]), "=r"(r[1]) : "r"(addr));
}
__device__ __forceinline__ void mma_bf16(float* c, const uint32_t* a, const uint32_t* b) {
    asm volatile("mma.sync.aligned.m16n8k16.row.col.f32.bf16.bf16.f32 "
                 "{%0,%1,%2,%3}, {%4,%5,%6,%7}, {%8,%9}, {%0,%1,%2,%3};"
                 : "+f"(c[0]), "+f"(c[1]), "+f"(c[2]), "+f"(c[3])
                 : "r"(a[0]), "r"(a[1]), "r"(a[2]), "r"(a[3]), "r"(b[0]), "r"(b[1]));
}

/* ---- pre-kernels ---- */
__global__ void init_out_kernel(float* out) {
    int i = blockIdx.x * blockDim.x + threadIdx.x;
    if (i < Bb * Kk) out[i] = __int_as_float(0x7f7fffff); /* FLT_MAX */
}
__global__ void split_x_kernel(const float* __restrict__ x) {
    int i = blockIdx.x * blockDim.x + threadIdx.x;
    if (i < Bb * Cc * Ll) {
        float v = x[i];
        __nv_bfloat16 hi = __float2bfloat16(v);
        g_x_hi[i] = hi;
        g_x_lo[i] = __float2bfloat16(v - __bfloat162float(hi));
    }
}
__global__ void split_sh_kernel(const float* __restrict__ sh) {
    int t = blockIdx.x * blockDim.x + threadIdx.x;  /* one (c,k) row each */
    if (t < Cc * Kk) {
        float sn = 0.0f;
        #pragma unroll 8
        for (int s = 0; s < Ss; s++) {
            float v = sh[t * Ss + s];
            __nv_bfloat16 hi = __float2bfloat16(v);
            g_sh_hi[t * Ss + s] = hi;
            g_sh_lo[t * Ss + s] = __float2bfloat16(v - __bfloat162float(hi));
            sn = fmaf(v, v, sn);
        }
        g_sn[t] = sn;
    }
}

/* ---- main kernel: warp-level bf16 mma.sync, fused epilogue ---- */
__global__ void __launch_bounds__(256, 2)
shapelet_hmma_kernel(float* __restrict__ out) {
    extern __shared__ char smem[];
    const int tid = threadIdx.x;
    const int lane = tid & 31;
    const int wid = tid >> 5;
    const int b = blockIdx.y;
    const int w0 = blockIdx.x * WT;
    const int kwarp = wid >> 1;   /* 0..3: warp's 32-row k block */
    const int wwarp = wid & 1;    /* 0..1: warp's 32-col w block */
    const int gid = lane >> 2;    /* 0..7 */
    const int qid = lane & 3;     /* 0..3 */

    __nv_bfloat16* xseg = (__nv_bfloat16*)(smem + SM_XSEG); /* xh|xo|xl|xlo, 160 each */
    float* xn = (float*)(smem + SM_XN);
    float* sn = (float*)(smem + SM_SN);

    /* preload all shapelet norms once (4 KB) */
    for (int i = tid; i < Cc * Kk; i += 256) sn[i] = g_sn[i];

    const uint32_t sb = smem_u32(smem);
    /* ldmatrix per-lane base addresses */
    const uint32_t aRow = (uint32_t)((kwarp * 32 + (lane & 15)) * RPB + ((lane & 16) ? 16 : 0));
    const uint32_t aAddrH = sb + SM_AH + aRow;
    const uint32_t aAddrL = sb + SM_AL + aRow;
    const uint32_t bRow = (uint32_t)((wwarp * 32 + (lane & 7)) * RPB + ((lane & 8) ? 16 : 0));
    const uint32_t bAddrH = sb + SM_BH + bRow;
    const uint32_t bAddrL = sb + SM_BL + bRow;

    float dist[2][4][4];
    #pragma unroll
    for (int mi = 0; mi < 2; mi++)
        #pragma unroll
        for (int ni = 0; ni < 4; ni++)
            #pragma unroll
            for (int v = 0; v < 4; v++) dist[mi][ni][v] = 0.0f;

    for (int c = 0; c < Cc; c++) {
        __syncthreads();  /* protect smem from previous channel's readers */

        /* ---- phase 1: stage x segments and A (shapelet) tiles ---- */
        for (int idx = tid; idx < 4 * 144; idx += 256) {
            int arr = idx / 144;           /* 0=xh 1=xo 2=xl 3=xlo */
            int i = idx - arr * 144;
            int g = w0 + i + (arr & 1);
            const __nv_bfloat16* src = (arr < 2) ? g_x_hi : g_x_lo;
            xseg[arr * 160 + i] = (g < Ll) ? src[(b * Cc + c) * Ll + g]
                                           : __nv_bfloat16(0.0f);
        }
        #pragma unroll
        for (int it = 0; it < 8; it++) {
            int task = it * 256 + tid;     /* 2048 uint4 tasks */
            int sp = task >> 10;
            int rem = task & 1023;
            int row = rem >> 3;
            int v4 = rem & 7;
            const uint4* src = (const uint4*)(sp ? g_sh_lo : g_sh_hi);
            uint4 v = src[(c * Kk + row) * 8 + v4];
            *(uint4*)(smem + (sp ? SM_AL : SM_AH) + row * RPB + v4 * 16) = v;
        }
        __syncthreads();

        /* ---- phase 2: build Toeplitz B tiles + window norms ---- */
        {
            int rt = tid >> 1;             /* 0..127 row-tasks */
            int half = tid & 1;
            int row = rt & 63;
            int sp = rt >> 6;
            const uint32_t* srcE = (const uint32_t*)(xseg + (sp ? 320 : 0));   /* aligned */
            const uint32_t* srcO = (const uint32_t*)(xseg + (sp ? 480 : 160)); /* +1 shift */
            const uint32_t* src = (row & 1) ? srcO : srcE;
            int base = row >> 1;
            uint32_t* dst = (uint32_t*)(smem + (sp ? SM_BL : SM_BH) + row * RPB);
            #pragma unroll
            for (int jj = 0; jj < 16; jj++) {
                int j = half * 16 + jj;
                dst[j] = src[base + j];
            }
        }
        if (tid < WT) {
            float t = 0.0f;
            #pragma unroll 16
            for (int s = 0; s < Ss; s++) {
                float v = __bfloat162float(xseg[tid + s]) + __bfloat162float(xseg[320 + tid + s]);
                t = fmaf(v, v, t);
            }
            xn[tid] = t;
        }
        __syncthreads();

        /* ---- phase 3: 24 HMMA x 4 k-steps, then fused epilogue ---- */
        float acc[2][4][4];
        #pragma unroll
        for (int mi = 0; mi < 2; mi++)
            #pragma unroll
            for (int ni = 0; ni < 4; ni++)
                #pragma unroll
                for (int v = 0; v < 4; v++) acc[mi][ni][v] = 0.0f;

        #pragma unroll
        for (int ks = 0; ks < 4; ks++) {
            uint32_t Ah[2][4], Al[2][4], Bh[4][2], Bl[4][2];
            #pragma unroll
            for (int mi = 0; mi < 2; mi++) {
                ldsm_x4(Ah[mi], aAddrH + mi * (16 * RPB) + ks * 32);
                ldsm_x4(Al[mi], aAddrL + mi * (16 * RPB) + ks * 32);
            }
            #pragma unroll
            for (int ni = 0; ni < 4; ni++) {
                ldsm_x2(Bh[ni], bAddrH + ni * (8 * RPB) + ks * 32);
                ldsm_x2(Bl[ni], bAddrL + ni * (8 * RPB) + ks * 32);
            }
            #pragma unroll
            for (int mi = 0; mi < 2; mi++)
                #pragma unroll
                for (int ni = 0; ni < 4; ni++) {
                    mma_bf16(acc[mi][ni], Ah[mi], Bh[ni]);  /* hi*hi */
                    mma_bf16(acc[mi][ni], Ah[mi], Bl[ni]);  /* hi*lo */
                    mma_bf16(acc[mi][ni], Al[mi], Bh[ni]);  /* lo*hi */
                }
        }

        /* epilogue: d2 = xn + sn - 2*cross; dist += sqrt(d2) */
        #pragma unroll
        for (int mi = 0; mi < 2; mi++) {
            int r0 = kwarp * 32 + mi * 16 + gid;
            float sn0 = sn[c * Kk + r0];
            float sn1 = sn[c * Kk + r0 + 8];
            #pragma unroll
            for (int ni = 0; ni < 4; ni++) {
                int c0 = wwarp * 32 + ni * 8 + 2 * qid;
                float x0 = xn[c0], x1 = xn[c0 + 1];
                float t00 = x0 + sn0, t01 = x1 + sn0;
                float t10 = x0 + sn1, t11 = x1 + sn1;
                float d0 = fmaxf(fmaf(-2.0f, acc[mi][ni][0], t00), 1e-12f);
                float d1 = fmaxf(fmaf(-2.0f, acc[mi][ni][1], t01), 1e-12f);
                float d2 = fmaxf(fmaf(-2.0f, acc[mi][ni][2], t10), 1e-12f);
                float d3 = fmaxf(fmaf(-2.0f, acc[mi][ni][3], t11), 1e-12f);
                dist[mi][ni][0] += d0 * rsqrtf(d0);
                dist[mi][ni][1] += d1 * rsqrtf(d1);
                dist[mi][ni][2] += d2 * rsqrtf(d2);
                dist[mi][ni][3] += d3 * rsqrtf(d3);
            }
        }
    }

    /* ---- min over windows (validity-masked), lane reduce, global atomicMin ---- */
    const float INF = __int_as_float(0x7f800000);
    #pragma unroll
    for (int mi = 0; mi < 2; mi++) {
        float m0 = INF, m1 = INF;
        #pragma unroll
        for (int ni = 0; ni < 4; ni++) {
            int wv = w0 + wwarp * 32 + ni * 8 + 2 * qid;
            if (wv < Ww)     { m0 = fminf(m0, dist[mi][ni][0]); m1 = fminf(m1, dist[mi][ni][2]); }
            if (wv + 1 < Ww) { m0 = fminf(m0, dist[mi][ni][1]); m1 = fminf(m1, dist[mi][ni][3]); }
        }
        m0 = fminf(m0, __shfl_xor_sync(0xFFFFFFFF, m0, 1));
        m0 = fminf(m0, __shfl_xor_sync(0xFFFFFFFF, m0, 2));
        m1 = fminf(m1, __shfl_xor_sync(0xFFFFFFFF, m1, 1));
        m1 = fminf(m1, __shfl_xor_sync(0xFFFFFFFF, m1, 2));
        if (qid == 0) {
            int r = kwarp * 32 + mi * 16 + gid;
            atomicMin((int*)&out[b * Kk + r],     __float_as_int(m0));
            atomicMin((int*)&out[b * Kk + r + 8], __float_as_int(m1));
        }
    }
}

extern "C" void kernel_launch(void* const* d_in, const int* in_sizes, int n_in,
                              void* d_out, int out_size) {
    const float* x  = (const float*)d_in[0];   /* (32, 8, 4096) */
    const float* sh = (const float*)d_in[1];   /* (8, 128, 64)  */
    float* out = (float*)d_out;                /* (32, 1, 128)  */

    cudaFuncSetAttribute(shapelet_hmma_kernel,
                         cudaFuncAttributeMaxDynamicSharedMemorySize, SM_TOTAL);

    init_out_kernel<<<(Bb * Kk + 255) / 256, 256>>>(out);
    split_x_kernel<<<(Bb * Cc * Ll + 255) / 256, 256>>>(x);
    split_sh_kernel<<<(Cc * Kk + 255) / 256, 256>>>(sh);

    dim3 grid(NWT, Bb);
    shapelet_hmma_kernel<<<grid, 256, SM_TOTAL>>>(out);
}

// round 6
// speedup vs baseline: 2.4742x; 1.7833x over previous
#include <cuda_runtime.h>
#include <cstdint>

#define Bb 32
#define Cc 8
#define Ll 4096
#define Kk 128
#define Ss 64
#define Ww (Ll - Ss + 1)          /* 4033 */
#define WT 64                     /* windows per CTA */
#define NWT ((Ww + WT - 1) / WT)  /* 64 */
#define PITCH 68                  /* A smem row pitch in floats (conflict-free) */

/* smem offsets in floats */
#define OFF_A(p)  ((p) * 8704)                 /* 128 x 68 per buffer */
#define OFF_XS(p) (17408 + (p) * 192)          /* 192-float x segment */
#define OFF_XN(p) (17792 + (p) * 64)           /* window norms */
#define OFF_SN    17920                        /* 1024 shapelet norms */
#define SMEM_FLOATS 18944
#define SMEM_BYTES (SMEM_FLOATS * 4)           /* 75776 */

__device__ float g_sn[Cc * Kk];

__device__ __forceinline__ float cvt_tf32(float v) {
    float r;
    asm("cvt.rna.tf32.f32 %0, %1;" : "=f"(r) : "f"(v));
    return r;
}
__device__ __forceinline__ void mma_tf32(float* c, const float* a, const float* b) {
    const uint32_t* A = reinterpret_cast<const uint32_t*>(a);
    const uint32_t* B = reinterpret_cast<const uint32_t*>(b);
    asm volatile("mma.sync.aligned.m16n8k8.row.col.f32.tf32.tf32.f32 "
                 "{%0,%1,%2,%3}, {%4,%5,%6,%7}, {%8,%9}, {%0,%1,%2,%3};"
                 : "+f"(c[0]), "+f"(c[1]), "+f"(c[2]), "+f"(c[3])
                 : "r"(A[0]), "r"(A[1]), "r"(A[2]), "r"(A[3]),
                   "r"(B[0]), "r"(B[1]));
}

__global__ void init_out_kernel(float* out) {
    int i = blockIdx.x * blockDim.x + threadIdx.x;
    if (i < Bb * Kk) out[i] = __int_as_float(0x7f7fffff); /* FLT_MAX */
}
__global__ void snorm_kernel(const float* __restrict__ sh) {
    int t = blockIdx.x * blockDim.x + threadIdx.x;
    if (t < Cc * Kk) {
        float s = 0.0f;
        #pragma unroll 8
        for (int i = 0; i < Ss; i++) { float v = sh[t * Ss + i]; s = fmaf(v, v, s); }
        g_sn[t] = s;
    }
}

__global__ void __launch_bounds__(256, 2)
shapelet_tf32_kernel(const float* __restrict__ x,
                     const float* __restrict__ sh,
                     float* __restrict__ out) {
    extern __shared__ float sm[];
    const int tid = threadIdx.x;
    const int lane = tid & 31;
    const int wid = tid >> 5;
    const int b = blockIdx.y;
    const int w0 = blockIdx.x * WT;
    const int kwarp = wid >> 1;   /* 0..3: 32 k-rows */
    const int wwarp = wid & 1;    /* 0..1: 32 w-cols */
    const int gid = lane >> 2;    /* 0..7 */
    const int qid = lane & 3;     /* 0..3 */

    /* preload shapelet norms (exact fp32) */
    #pragma unroll
    for (int i = tid; i < Cc * Kk; i += 256) sm[OFF_SN + i] = g_sn[i];

    float dist[2][4][4];
    #pragma unroll
    for (int mi = 0; mi < 2; mi++)
        #pragma unroll
        for (int ni = 0; ni < 4; ni++)
            #pragma unroll
            for (int v = 0; v < 4; v++) dist[mi][ni][v] = 0.0f;

    /* ---------- stage channel 0 into buffer 0 ---------- */
    {
        const float* xrow = x + (b * Cc + 0) * Ll;
        const float4* shc4 = (const float4*)(sh + 0 * Kk * Ss);
        #pragma unroll
        for (int it = 0; it < 8; it++) {
            int t = it * 256 + tid;
            int row = t >> 4, v4 = t & 15;
            float4 v = shc4[row * 16 + v4];
            v.x = cvt_tf32(v.x); v.y = cvt_tf32(v.y);
            v.z = cvt_tf32(v.z); v.w = cvt_tf32(v.w);
            *(float4*)&sm[OFF_A(0) + row * PITCH + v4 * 4] = v;
        }
        if (tid < 192) {
            int g = w0 + tid;
            sm[OFF_XS(0) + tid] = cvt_tf32((g < Ll) ? xrow[g] : 0.0f);
        }
        if (tid < WT) {
            int w = w0 + tid;
            float t = 0.0f;
            #pragma unroll 16
            for (int s = 0; s < Ss; s++) {
                float v = (w + s < Ll) ? xrow[w + s] : 0.0f;
                t = fmaf(v, v, t);
            }
            sm[OFF_XN(0) + tid] = t;
        }
    }
    __syncthreads();

    const int r0base = kwarp * 32 + gid;        /* + mi*16 (+8) for rows */
    const int cbase = wwarp * 32 + 2 * qid;     /* + ni*8 (+1) for cols  */

    #pragma unroll 1
    for (int cc = 0; cc < Cc; cc++) {
        const int p = cc & 1;

        /* ---------- stage channel cc+1 into the other buffer ---------- */
        if (cc < Cc - 1) {
            const float* xrow = x + (b * Cc + cc + 1) * Ll;
            const float4* shc4 = (const float4*)(sh + (cc + 1) * Kk * Ss);
            #pragma unroll
            for (int it = 0; it < 8; it++) {
                int t = it * 256 + tid;
                int row = t >> 4, v4 = t & 15;
                float4 v = shc4[row * 16 + v4];
                v.x = cvt_tf32(v.x); v.y = cvt_tf32(v.y);
                v.z = cvt_tf32(v.z); v.w = cvt_tf32(v.w);
                *(float4*)&sm[OFF_A(p ^ 1) + row * PITCH + v4 * 4] = v;
            }
            if (tid < 192) {
                int g = w0 + tid;
                sm[OFF_XS(p ^ 1) + tid] = cvt_tf32((g < Ll) ? xrow[g] : 0.0f);
            }
            if (tid < WT) {
                int w = w0 + tid;
                float t = 0.0f;
                #pragma unroll 16
                for (int s = 0; s < Ss; s++) {
                    float v = (w + s < Ll) ? xrow[w + s] : 0.0f;
                    t = fmaf(v, v, t);
                }
                sm[OFF_XN(p ^ 1) + tid] = t;
            }
        }

        /* ---------- compute channel cc from buffer p ---------- */
        float acc[2][4][4];
        #pragma unroll
        for (int mi = 0; mi < 2; mi++)
            #pragma unroll
            for (int ni = 0; ni < 4; ni++)
                #pragma unroll
                for (int v = 0; v < 4; v++) acc[mi][ni][v] = 0.0f;

        const float* As = &sm[OFF_A(p)];
        const float* Xs = &sm[OFF_XS(p)];

        #pragma unroll
        for (int ks = 0; ks < 8; ks++) {
            const int col = ks * 8 + qid;
            float a[2][4];
            #pragma unroll
            for (int mi = 0; mi < 2; mi++) {
                int r = (r0base + mi * 16) * PITCH;
                a[mi][0] = As[r + col];
                a[mi][1] = As[r + 8 * PITCH + col];
                a[mi][2] = As[r + col + 4];
                a[mi][3] = As[r + 8 * PITCH + col + 4];
            }
            float bf[4][2];
            #pragma unroll
            for (int ni = 0; ni < 4; ni++) {
                int widx = wwarp * 32 + ni * 8 + gid + ks * 8 + qid;
                bf[ni][0] = Xs[widx];
                bf[ni][1] = Xs[widx + 4];
            }
            #pragma unroll
            for (int mi = 0; mi < 2; mi++)
                #pragma unroll
                for (int ni = 0; ni < 4; ni++)
                    mma_tf32(acc[mi][ni], a[mi], bf[ni]);
        }

        /* epilogue: d2 = xn + sn - 2*cross; dist += sqrt(d2) */
        #pragma unroll
        for (int ni = 0; ni < 4; ni++) {
            float x0 = sm[OFF_XN(p) + cbase + ni * 8];
            float x1 = sm[OFF_XN(p) + cbase + ni * 8 + 1];
            #pragma unroll
            for (int mi = 0; mi < 2; mi++) {
                float sn0 = sm[OFF_SN + cc * Kk + r0base + mi * 16];
                float sn1 = sm[OFF_SN + cc * Kk + r0base + mi * 16 + 8];
                float d0 = fmaxf(fmaf(-2.0f, acc[mi][ni][0], x0 + sn0), 1e-12f);
                float d1 = fmaxf(fmaf(-2.0f, acc[mi][ni][1], x1 + sn0), 1e-12f);
                float d2 = fmaxf(fmaf(-2.0f, acc[mi][ni][2], x0 + sn1), 1e-12f);
                float d3 = fmaxf(fmaf(-2.0f, acc[mi][ni][3], x1 + sn1), 1e-12f);
                dist[mi][ni][0] += d0 * rsqrtf(d0);
                dist[mi][ni][1] += d1 * rsqrtf(d1);
                dist[mi][ni][2] += d2 * rsqrtf(d2);
                dist[mi][ni][3] += d3 * rsqrtf(d3);
            }
        }
        __syncthreads();
    }

    /* ---- min over valid windows, lane reduce over qid, global atomicMin ---- */
    const float INF = __int_as_float(0x7f800000);
    #pragma unroll
    for (int mi = 0; mi < 2; mi++) {
        float m0 = INF, m1 = INF;
        #pragma unroll
        for (int ni = 0; ni < 4; ni++) {
            int wv = w0 + cbase + ni * 8;
            if (wv < Ww)     { m0 = fminf(m0, dist[mi][ni][0]); m1 = fminf(m1, dist[mi][ni][2]); }
            if (wv + 1 < Ww) { m0 = fminf(m0, dist[mi][ni][1]); m1 = fminf(m1, dist[mi][ni][3]); }
        }
        m0 = fminf(m0, __shfl_xor_sync(0xFFFFFFFF, m0, 1));
        m0 = fminf(m0, __shfl_xor_sync(0xFFFFFFFF, m0, 2));
        m1 = fminf(m1, __shfl_xor_sync(0xFFFFFFFF, m1, 1));
        m1 = fminf(m1, __shfl_xor_sync(0xFFFFFFFF, m1, 2));
        if (qid == 0) {
            int r = r0base + mi * 16;
            atomicMin((int*)&out[b * Kk + r],     __float_as_int(m0));
            atomicMin((int*)&out[b * Kk + r + 8], __float_as_int(m1));
        }
    }
}

extern "C" void kernel_launch(void* const* d_in, const int* in_sizes, int n_in,
                              void* d_out, int out_size) {
    const float* x  = (const float*)d_in[0];   /* (32, 8, 4096) */
    const float* sh = (const float*)d_in[1];   /* (8, 128, 64)  */
    float* out = (float*)d_out;                /* (32, 1, 128)  */

    cudaFuncSetAttribute(shapelet_tf32_kernel,
                         cudaFuncAttributeMaxDynamicSharedMemorySize, SMEM_BYTES);

    init_out_kernel<<<(Bb * Kk + 255) / 256, 256>>>(out);
    snorm_kernel<<<(Cc * Kk + 255) / 256, 256>>>(sh);

    dim3 grid(NWT, Bb);
    shapelet_tf32_kernel<<<grid, 256, SMEM_BYTES>>>(x, sh, out);
}

// round 9
// speedup vs baseline: 2.8389x; 1.1474x over previous
#include <cuda_runtime.h>
#include <cstdint>

#define Bb 32
#define Cc 8
#define Ll 4096
#define Kk 128
#define Ss 64
#define Ww (Ll - Ss + 1)          /* 4033 */
#define WT 64                     /* windows per CTA */
#define NWT ((Ww + WT - 1) / WT)  /* 64 */
#define PITCH 68                  /* A smem row pitch in floats (conflict-free) */

/* smem offsets in floats */
#define OFF_A(p)  ((p) * 8704)                 /* 128 x 68 per buffer */
#define OFF_XS(p) (17408 + (p) * 192)          /* 192-float x segment */
#define OFF_XN(p) (17792 + (p) * 64)           /* window norms */
#define OFF_SN    17920                        /* 1024 shapelet norms */
#define SMEM_FLOATS 18944
#define SMEM_BYTES (SMEM_FLOATS * 4)           /* 75776 */

__device__ float g_sn[Cc * Kk];

__device__ __forceinline__ uint32_t smem_u32(const void* p) {
    uint32_t a;
    asm("{ .reg .u64 t; cvta.to.shared.u64 t, %1; cvt.u32.u64 %0, t; }" : "=r"(a) : "l"(p));
    return a;
}
__device__ __forceinline__ void cp_async16(uint32_t dst, const void* src) {
    asm volatile("cp.async.ca.shared.global [%0], [%1], 16;"
                 :: "r"(dst), "l"(src) : "memory");
}
__device__ __forceinline__ void cp_async_commit() {
    asm volatile("cp.async.commit_group;" ::: "memory");
}
__device__ __forceinline__ void cp_async_wait0() {
    asm volatile("cp.async.wait_group 0;" ::: "memory");
}
__device__ __forceinline__ float sqrt_approx(float v) {
    float r;
    asm("sqrt.approx.f32 %0, %1;" : "=f"(r) : "f"(v));
    return r;
}
__device__ __forceinline__ void mma_tf32(float* c, const float* a, const float* b) {
    const uint32_t* A = reinterpret_cast<const uint32_t*>(a);
    const uint32_t* B = reinterpret_cast<const uint32_t*>(b);
    asm volatile("mma.sync.aligned.m16n8k8.row.col.f32.tf32.tf32.f32 "
                 "{%0,%1,%2,%3}, {%4,%5,%6,%7}, {%8,%9}, {%0,%1,%2,%3};"
                 : "+f"(c[0]), "+f"(c[1]), "+f"(c[2]), "+f"(c[3])
                 : "r"(A[0]), "r"(A[1]), "r"(A[2]), "r"(A[3]),
                   "r"(B[0]), "r"(B[1]));
}

/* one prep kernel: init out to FLT_MAX + exact shapelet norms */
__global__ void prep_kernel(const float* __restrict__ sh, float* __restrict__ out) {
    int i = blockIdx.x * blockDim.x + threadIdx.x;
    if (i < Bb * Kk) out[i] = __int_as_float(0x7f7fffff);
    if (i < Cc * Kk) {
        float s = 0.0f;
        #pragma unroll 8
        for (int j = 0; j < Ss; j++) { float v = sh[i * Ss + j]; s = fmaf(v, v, s); }
        g_sn[i] = s;
    }
}

__global__ void __launch_bounds__(256, 2)
shapelet_tf32_kernel(const float* __restrict__ x,
                     const float* __restrict__ sh,
                     float* __restrict__ out) {
    extern __shared__ float sm[];
    const uint32_t sb = smem_u32(sm);
    const int tid = threadIdx.x;
    const int lane = tid & 31;
    const int wid = tid >> 5;
    const int b = blockIdx.y;
    const int w0 = blockIdx.x * WT;
    const int kwarp = wid >> 1;   /* 0..3: 32 k-rows */
    const int wwarp = wid & 1;    /* 0..1: 32 w-cols */
    const int gid = lane >> 2;    /* 0..7 */
    const int qid = lane & 3;     /* 0..3 */

    /* preload shapelet norms (exact fp32) */
    #pragma unroll
    for (int i = tid; i < Cc * Kk; i += 256) sm[OFF_SN + i] = g_sn[i];

    float dist[2][4][4];
    #pragma unroll
    for (int mi = 0; mi < 2; mi++)
        #pragma unroll
        for (int ni = 0; ni < 4; ni++)
            #pragma unroll
            for (int v = 0; v < 4; v++) dist[mi][ni][v] = 0.0f;

    /* A-tile async stage: 2048 16B chunks per channel, 8 per thread */
    const int a_row = tid >> 4;          /* base row (of 16-task stripe) */
    const int a_v4  = tid & 15;

    /* ---------- stage channel 0 into buffer 0 ---------- */
    {
        const float* xrow = x + (b * Cc + 0) * Ll;
        const float* shc = sh + 0 * Kk * Ss;
        #pragma unroll
        for (int it = 0; it < 8; it++) {
            int row = it * 16 + a_row;
            cp_async16(sb + (OFF_A(0) + row * PITCH + a_v4 * 4) * 4,
                       shc + row * Ss + a_v4 * 4);
        }
        cp_async_commit();
        if (tid < 192) {
            int g = w0 + tid;
            sm[OFF_XS(0) + tid] = (g < Ll) ? xrow[g] : 0.0f;
        }
        if (tid < WT) {
            int w = w0 + tid;
            float t = 0.0f;
            #pragma unroll 16
            for (int s = 0; s < Ss; s++) {
                float v = (w + s < Ll) ? xrow[w + s] : 0.0f;
                t = fmaf(v, v, t);
            }
            sm[OFF_XN(0) + tid] = t;
        }
    }
    cp_async_wait0();
    __syncthreads();

    const int r0base = kwarp * 32 + gid;        /* + mi*16 (+8) for rows */
    const int cbase = wwarp * 32 + 2 * qid;     /* + ni*8 (+1) for cols  */

    #pragma unroll 1
    for (int cc = 0; cc < Cc; cc++) {
        const int p = cc & 1;

        /* ---------- stage channel cc+1 into the other buffer (async) ---------- */
        if (cc < Cc - 1) {
            const float* xrow = x + (b * Cc + cc + 1) * Ll;
            const float* shc = sh + (cc + 1) * Kk * Ss;
            #pragma unroll
            for (int it = 0; it < 8; it++) {
                int row = it * 16 + a_row;
                cp_async16(sb + (OFF_A(p ^ 1) + row * PITCH + a_v4 * 4) * 4,
                           shc + row * Ss + a_v4 * 4);
            }
            cp_async_commit();
            if (tid < 192) {
                int g = w0 + tid;
                sm[OFF_XS(p ^ 1) + tid] = (g < Ll) ? xrow[g] : 0.0f;
            }
            if (tid < WT) {
                int w = w0 + tid;
                float t = 0.0f;
                #pragma unroll 16
                for (int s = 0; s < Ss; s++) {
                    float v = (w + s < Ll) ? xrow[w + s] : 0.0f;
                    t = fmaf(v, v, t);
                }
                sm[OFF_XN(p ^ 1) + tid] = t;
            }
        }

        /* ---------- compute channel cc from buffer p ---------- */
        float acc[2][4][4];
        #pragma unroll
        for (int mi = 0; mi < 2; mi++)
            #pragma unroll
            for (int ni = 0; ni < 4; ni++)
                #pragma unroll
                for (int v = 0; v < 4; v++) acc[mi][ni][v] = 0.0f;

        const float* As = &sm[OFF_A(p)];
        const float* Xs = &sm[OFF_XS(p)];

        #pragma unroll
        for (int ks = 0; ks < 8; ks++) {
            const int col = ks * 8 + qid;
            float a[2][4];
            #pragma unroll
            for (int mi = 0; mi < 2; mi++) {
                int r = (r0base + mi * 16) * PITCH;
                a[mi][0] = As[r + col];
                a[mi][1] = As[r + 8 * PITCH + col];
                a[mi][2] = As[r + col + 4];
                a[mi][3] = As[r + 8 * PITCH + col + 4];
            }
            float bf[4][2];
            #pragma unroll
            for (int ni = 0; ni < 4; ni++) {
                int widx = wwarp * 32 + ni * 8 + gid + ks * 8 + qid;
                bf[ni][0] = Xs[widx];
                bf[ni][1] = Xs[widx + 4];
            }
            #pragma unroll
            for (int mi = 0; mi < 2; mi++)
                #pragma unroll
                for (int ni = 0; ni < 4; ni++)
                    mma_tf32(acc[mi][ni], a[mi], bf[ni]);
        }

        /* epilogue: d2 = xn + sn - 2*cross; dist += sqrt(d2) */
        #pragma unroll
        for (int ni = 0; ni < 4; ni++) {
            float x0 = sm[OFF_XN(p) + cbase + ni * 8];
            float x1 = sm[OFF_XN(p) + cbase + ni * 8 + 1];
            #pragma unroll
            for (int mi = 0; mi < 2; mi++) {
                float sn0 = sm[OFF_SN + cc * Kk + r0base + mi * 16];
                float sn1 = sm[OFF_SN + cc * Kk + r0base + mi * 16 + 8];
                float d0 = fmaxf(fmaf(-2.0f, acc[mi][ni][0], x0 + sn0), 1e-12f);
                float d1 = fmaxf(fmaf(-2.0f, acc[mi][ni][1], x1 + sn0), 1e-12f);
                float d2 = fmaxf(fmaf(-2.0f, acc[mi][ni][2], x0 + sn1), 1e-12f);
                float d3 = fmaxf(fmaf(-2.0f, acc[mi][ni][3], x1 + sn1), 1e-12f);
                dist[mi][ni][0] += sqrt_approx(d0);
                dist[mi][ni][1] += sqrt_approx(d1);
                dist[mi][ni][2] += sqrt_approx(d2);
                dist[mi][ni][3] += sqrt_approx(d3);
            }
        }
        cp_async_wait0();
        __syncthreads();
    }

    /* ---- min over valid windows, lane reduce over qid, global atomicMin ---- */
    const float INF = __int_as_float(0x7f800000);
    #pragma unroll
    for (int mi = 0; mi < 2; mi++) {
        float m0 = INF, m1 = INF;
        #pragma unroll
        for (int ni = 0; ni < 4; ni++) {
            int wv = w0 + cbase + ni * 8;
            if (wv < Ww)     { m0 = fminf(m0, dist[mi][ni][0]); m1 = fminf(m1, dist[mi][ni][2]); }
            if (wv + 1 < Ww) { m0 = fminf(m0, dist[mi][ni][1]); m1 = fminf(m1, dist[mi][ni][3]); }
        }
        m0 = fminf(m0, __shfl_xor_sync(0xFFFFFFFF, m0, 1));
        m0 = fminf(m0, __shfl_xor_sync(0xFFFFFFFF, m0, 2));
        m1 = fminf(m1, __shfl_xor_sync(0xFFFFFFFF, m1, 1));
        m1 = fminf(m1, __shfl_xor_sync(0xFFFFFFFF, m1, 2));
        if (qid == 0) {
            int r = r0base + mi * 16;
            atomicMin((int*)&out[b * Kk + r],     __float_as_int(m0));
            atomicMin((int*)&out[b * Kk + r + 8], __float_as_int(m1));
        }
    }
}

extern "C" void kernel_launch(void* const* d_in, const int* in_sizes, int n_in,
                              void* d_out, int out_size) {
    const float* x  = (const float*)d_in[0];   /* (32, 8, 4096) */
    const float* sh = (const float*)d_in[1];   /* (8, 128, 64)  */
    float* out = (float*)d_out;                /* (32, 1, 128)  */

    cudaFuncSetAttribute(shapelet_tf32_kernel,
                         cudaFuncAttributeMaxDynamicSharedMemorySize, SMEM_BYTES);

    prep_kernel<<<(Bb * Kk + 255) / 256, 256>>>(sh, out);

    dim3 grid(NWT, Bb);
    shapelet_tf32_kernel<<<grid, 256, SMEM_BYTES>>>(x, sh, out);
}